// round 5
// baseline (speedup 1.0000x reference)
#include <cuda_runtime.h>
#include <cuda_bf16.h>
#include <mma.h>
#include <cstdint>

using namespace nvcuda;

// ---------------- problem constants ----------------
#define BATCH   8
#define NT      8192
#define NS      2048
#define NTOT    (BATCH * NT)      // 65536 target rows
#define C_TGT   128
#define C_SRC   256
#define C_IN    384               // C_TGT + C_SRC
#define C_HID   256
#define C_OUT   128

// ---------------- device scratch (no allocs allowed) ----------------
__device__ int   g_knn_idx[NTOT * 3];
__device__ float g_knn_w  [NTOT * 3];
__device__ float g_interp [NTOT * C_SRC];   // 64 MB
__device__ float g_hidden [NTOT * C_HID];   // 64 MB

// ============================================================
// Kernel 1: brute-force 3-NN per target within its batch.
// One block = 256 targets of one batch; pos_source of the batch in smem.
// ============================================================
__global__ __launch_bounds__(256)
void knn_kernel(const float* __restrict__ pos_t, const float* __restrict__ pos_s)
{
    __shared__ float4 sp[NS];             // 32 KB
    const int b    = blockIdx.x >> 5;     // NT/256 = 32 tiles per batch
    const int tile = blockIdx.x & 31;

    const float* ps = pos_s + (size_t)b * NS * 3;
    for (int s = threadIdx.x; s < NS; s += 256) {
        sp[s] = make_float4(ps[3*s], ps[3*s+1], ps[3*s+2], 0.f);
    }
    __syncthreads();

    const int t = (b * 32 + tile) * 256 + threadIdx.x;   // global target row
    const float tx = pos_t[3*t], ty = pos_t[3*t+1], tz = pos_t[3*t+2];

    float d0 = 1e30f, d1 = 1e30f, d2 = 1e30f;
    int   i0 = 0,     i1 = 0,     i2 = 0;

    #pragma unroll 4
    for (int s = 0; s < NS; ++s) {
        float4 p = sp[s];
        float dx = tx - p.x, dy = ty - p.y, dz = tz - p.z;
        float d  = fmaf(dz, dz, fmaf(dy, dy, dx * dx));
        if (d < d2) {
            if (d < d1) {
                d2 = d1; i2 = i1;
                if (d < d0) { d1 = d0; i1 = i0; d0 = d; i0 = s; }
                else        { d1 = d;  i1 = s; }
            } else { d2 = d; i2 = s; }
        }
    }

    const float w0 = 1.f / fmaxf(d0, 1e-16f);
    const float w1 = 1.f / fmaxf(d1, 1e-16f);
    const float w2 = 1.f / fmaxf(d2, 1e-16f);
    const float inv = 1.f / (w0 + w1 + w2);

    g_knn_w[3*t+0] = w0 * inv;
    g_knn_w[3*t+1] = w1 * inv;
    g_knn_w[3*t+2] = w2 * inv;
    g_knn_idx[3*t+0] = b * NS + i0;
    g_knn_idx[3*t+1] = b * NS + i1;
    g_knn_idx[3*t+2] = b * NS + i2;
}

// ============================================================
// Kernel 2: interpolation gather. One warp per target row, 256 channels.
// x_source (16 MB) stays L2-resident -> write-bound.
// ============================================================
__global__ __launch_bounds__(256)
void interp_kernel(const float* __restrict__ xs)
{
    const int row  = blockIdx.x * 8 + (threadIdx.x >> 5);
    const int lane = threadIdx.x & 31;

    const int   i0 = g_knn_idx[3*row+0];
    const int   i1 = g_knn_idx[3*row+1];
    const int   i2 = g_knn_idx[3*row+2];
    const float w0 = g_knn_w[3*row+0];
    const float w1 = g_knn_w[3*row+1];
    const float w2 = g_knn_w[3*row+2];

    const float4* s0 = (const float4*)(xs + (size_t)i0 * C_SRC);
    const float4* s1 = (const float4*)(xs + (size_t)i1 * C_SRC);
    const float4* s2 = (const float4*)(xs + (size_t)i2 * C_SRC);
    float4* dst = (float4*)(g_interp + (size_t)row * C_SRC);

    #pragma unroll
    for (int h = 0; h < 2; ++h) {
        const int c = lane + h * 32;            // float4 index, 64 per row
        float4 a = s0[c], b = s1[c], d = s2[c];
        float4 r;
        r.x = w0*a.x + w1*b.x + w2*d.x;
        r.y = w0*a.y + w1*b.y + w2*d.y;
        r.z = w0*a.z + w1*b.z + w2*d.z;
        r.w = w0*a.w + w1*b.w + w2*d.w;
        dst[c] = r;
    }
}

// ============================================================
// Shared GEMM machinery: 128x128 block tile, 8 warps (4x2), KC=32,
// wmma tf32 m16n16k8. A is read from segmented sources (virtual concat).
// ============================================================
#define SA_LD 36      // 128 x 36 floats
#define SB_LD 132     // 32 x 132 floats
#define SA_SZ (128 * SA_LD)   // 4608
#define SB_SZ (32 * SB_LD)    // 4224

using FragA = wmma::fragment<wmma::matrix_a, 16, 16, 8, wmma::precision::tf32, wmma::row_major>;
using FragB = wmma::fragment<wmma::matrix_b, 16, 16, 8, wmma::precision::tf32, wmma::row_major>;
using FragC = wmma::fragment<wmma::accumulator, 16, 16, 8, float>;

// ------------------------------------------------------------
// GEMM1: h = relu([x_target | interp] @ W1 + b1)   (K=384, N=256)
// ------------------------------------------------------------
__global__ __launch_bounds__(256)
void gemm1_kernel(const float* __restrict__ xt,
                  const float* __restrict__ W1,
                  const float* __restrict__ b1)
{
    __shared__ float smem[SA_SZ + SB_SZ];
    float* sA = smem;
    float* sB = smem + SA_SZ;

    const int m0 = blockIdx.x * 128;
    const int n0 = blockIdx.y * 128;
    const int tid = threadIdx.x;
    const int w   = tid >> 5;
    const int warp_m = w & 3;    // 4 row groups of 32
    const int warp_n = w >> 2;   // 2 col groups of 64

    FragA fa[2];
    FragB fb[4];
    FragC fc[2][4];
    #pragma unroll
    for (int i = 0; i < 2; ++i)
        #pragma unroll
        for (int j = 0; j < 4; ++j)
            wmma::fill_fragment(fc[i][j], 0.f);

    for (int kc = 0; kc < C_IN; kc += 32) {
        // --- stage A tile (128x32) ---
        #pragma unroll
        for (int tI = 0; tI < 4; ++tI) {
            const int i4 = tid + tI * 256;          // 1024 float4
            const int r  = i4 >> 3;
            const int c4 = (i4 & 7) << 2;
            const float* src = (kc < C_TGT)
                ? (xt       + (size_t)(m0 + r) * C_TGT + kc + c4)
                : (g_interp + (size_t)(m0 + r) * C_SRC + (kc - C_TGT) + c4);
            float4 v = *(const float4*)src;
            float* d = &sA[r * SA_LD + c4];
            d[0] = wmma::__float_to_tf32(v.x);
            d[1] = wmma::__float_to_tf32(v.y);
            d[2] = wmma::__float_to_tf32(v.z);
            d[3] = wmma::__float_to_tf32(v.w);
        }
        // --- stage B tile (32x128) ---
        #pragma unroll
        for (int tI = 0; tI < 4; ++tI) {
            const int i4 = tid + tI * 256;
            const int r  = i4 >> 5;
            const int c4 = (i4 & 31) << 2;
            float4 v = *(const float4*)(W1 + (size_t)(kc + r) * C_HID + n0 + c4);
            float* d = &sB[r * SB_LD + c4];
            d[0] = wmma::__float_to_tf32(v.x);
            d[1] = wmma::__float_to_tf32(v.y);
            d[2] = wmma::__float_to_tf32(v.z);
            d[3] = wmma::__float_to_tf32(v.w);
        }
        __syncthreads();

        #pragma unroll
        for (int kk = 0; kk < 4; ++kk) {
            #pragma unroll
            for (int i = 0; i < 2; ++i)
                wmma::load_matrix_sync(fa[i], &sA[(warp_m*32 + i*16) * SA_LD + kk*8], SA_LD);
            #pragma unroll
            for (int j = 0; j < 4; ++j)
                wmma::load_matrix_sync(fb[j], &sB[(kk*8) * SB_LD + warp_n*64 + j*16], SB_LD);
            #pragma unroll
            for (int i = 0; i < 2; ++i)
                #pragma unroll
                for (int j = 0; j < 4; ++j)
                    wmma::mma_sync(fc[i][j], fa[i], fb[j], fc[i][j]);
        }
        __syncthreads();
    }

    // --- epilogue: bias + relu -> g_hidden ---
    float* wb = &smem[w * 1024];          // 16x64 staging per warp
    const int gm_base = m0 + warp_m * 32;
    const int gn_base = n0 + warp_n * 64;
    const int lane = tid & 31;
    #pragma unroll
    for (int i = 0; i < 2; ++i) {
        #pragma unroll
        for (int j = 0; j < 4; ++j)
            wmma::store_matrix_sync(wb + j*16, fc[i][j], 64, wmma::mem_row_major);
        __syncwarp();
        #pragma unroll
        for (int e = lane; e < 256; e += 32) {
            const int rr = e >> 4;
            const int cc = (e & 15) << 2;
            float4 v = *(float4*)(wb + rr*64 + cc);
            const int gn = gn_base + cc;
            v.x = fmaxf(v.x + b1[gn+0], 0.f);
            v.y = fmaxf(v.y + b1[gn+1], 0.f);
            v.z = fmaxf(v.z + b1[gn+2], 0.f);
            v.w = fmaxf(v.w + b1[gn+3], 0.f);
            *(float4*)(&g_hidden[(size_t)(gm_base + i*16 + rr) * C_HID + gn]) = v;
        }
        __syncwarp();
    }
}

// ------------------------------------------------------------
// GEMM2: out = relu([h | x_target | interp] @ [W2; Ws] + (b2+bs))
// K=640, N=128
// ------------------------------------------------------------
__global__ __launch_bounds__(256)
void gemm2_kernel(const float* __restrict__ xt,
                  const float* __restrict__ W2,
                  const float* __restrict__ b2,
                  const float* __restrict__ Ws,
                  const float* __restrict__ bs,
                  float* __restrict__ out)
{
    __shared__ float smem[SA_SZ + SB_SZ];
    float* sA = smem;
    float* sB = smem + SA_SZ;

    const int m0 = blockIdx.x * 128;
    const int tid = threadIdx.x;
    const int w   = tid >> 5;
    const int warp_m = w & 3;
    const int warp_n = w >> 2;

    FragA fa[2];
    FragB fb[4];
    FragC fc[2][4];
    #pragma unroll
    for (int i = 0; i < 2; ++i)
        #pragma unroll
        for (int j = 0; j < 4; ++j)
            wmma::fill_fragment(fc[i][j], 0.f);

    for (int kc = 0; kc < 640; kc += 32) {
        // segmented A source: [hidden(256) | x_target(128) | interp(256)]
        const float* abase; int astride, aoff;
        if      (kc < 256) { abase = g_hidden; astride = C_HID; aoff = kc;       }
        else if (kc < 384) { abase = xt;       astride = C_TGT; aoff = kc - 256; }
        else               { abase = g_interp; astride = C_SRC; aoff = kc - 384; }
        // segmented B source: rows [W2(256) ; Ws(384)]
        const float* bbase; int boff;
        if (kc < 256) { bbase = W2; boff = kc;       }
        else          { bbase = Ws; boff = kc - 256; }

        #pragma unroll
        for (int tI = 0; tI < 4; ++tI) {
            const int i4 = tid + tI * 256;
            const int r  = i4 >> 3;
            const int c4 = (i4 & 7) << 2;
            float4 v = *(const float4*)(abase + (size_t)(m0 + r) * astride + aoff + c4);
            float* d = &sA[r * SA_LD + c4];
            d[0] = wmma::__float_to_tf32(v.x);
            d[1] = wmma::__float_to_tf32(v.y);
            d[2] = wmma::__float_to_tf32(v.z);
            d[3] = wmma::__float_to_tf32(v.w);
        }
        #pragma unroll
        for (int tI = 0; tI < 4; ++tI) {
            const int i4 = tid + tI * 256;
            const int r  = i4 >> 5;
            const int c4 = (i4 & 31) << 2;
            float4 v = *(const float4*)(bbase + (size_t)(boff + r) * C_OUT + c4);
            float* d = &sB[r * SB_LD + c4];
            d[0] = wmma::__float_to_tf32(v.x);
            d[1] = wmma::__float_to_tf32(v.y);
            d[2] = wmma::__float_to_tf32(v.z);
            d[3] = wmma::__float_to_tf32(v.w);
        }
        __syncthreads();

        #pragma unroll
        for (int kk = 0; kk < 4; ++kk) {
            #pragma unroll
            for (int i = 0; i < 2; ++i)
                wmma::load_matrix_sync(fa[i], &sA[(warp_m*32 + i*16) * SA_LD + kk*8], SA_LD);
            #pragma unroll
            for (int j = 0; j < 4; ++j)
                wmma::load_matrix_sync(fb[j], &sB[(kk*8) * SB_LD + warp_n*64 + j*16], SB_LD);
            #pragma unroll
            for (int i = 0; i < 2; ++i)
                #pragma unroll
                for (int j = 0; j < 4; ++j)
                    wmma::mma_sync(fc[i][j], fa[i], fb[j], fc[i][j]);
        }
        __syncthreads();
    }

    // epilogue: (b2+bs) + relu -> out
    float* wb = &smem[w * 1024];
    const int gm_base = m0 + warp_m * 32;
    const int gn_base = warp_n * 64;
    const int lane = tid & 31;
    #pragma unroll
    for (int i = 0; i < 2; ++i) {
        #pragma unroll
        for (int j = 0; j < 4; ++j)
            wmma::store_matrix_sync(wb + j*16, fc[i][j], 64, wmma::mem_row_major);
        __syncwarp();
        #pragma unroll
        for (int e = lane; e < 256; e += 32) {
            const int rr = e >> 4;
            const int cc = (e & 15) << 2;
            float4 v = *(float4*)(wb + rr*64 + cc);
            const int gn = gn_base + cc;
            v.x = fmaxf(v.x + b2[gn+0] + bs[gn+0], 0.f);
            v.y = fmaxf(v.y + b2[gn+1] + bs[gn+1], 0.f);
            v.z = fmaxf(v.z + b2[gn+2] + bs[gn+2], 0.f);
            v.w = fmaxf(v.w + b2[gn+3] + bs[gn+3], 0.f);
            *(float4*)(&out[(size_t)(gm_base + i*16 + rr) * C_OUT + gn]) = v;
        }
        __syncwarp();
    }
}

// ============================================================
// Launch. Input order (metadata): x_target, pos_target, batch_target,
// x_source, pos_source, batch_source, W1, b1, W2, b2, Ws, bs
// ============================================================
extern "C" void kernel_launch(void* const* d_in, const int* in_sizes, int n_in,
                              void* d_out, int out_size)
{
    const float* xt = (const float*)d_in[0];
    const float* pt = (const float*)d_in[1];
    const float* xs = (const float*)d_in[3];
    const float* ps = (const float*)d_in[4];
    const float* W1 = (const float*)d_in[6];
    const float* b1 = (const float*)d_in[7];
    const float* W2 = (const float*)d_in[8];
    const float* b2 = (const float*)d_in[9];
    const float* Ws = (const float*)d_in[10];
    const float* bs = (const float*)d_in[11];
    float* out = (float*)d_out;

    knn_kernel   <<<BATCH * (NT / 256), 256>>>(pt, ps);
    interp_kernel<<<NTOT / 8, 256>>>(xs);
    gemm1_kernel <<<dim3(NTOT / 128, C_HID / 128), 256>>>(xt, W1, b1);
    gemm2_kernel <<<dim3(NTOT / 128, 1), 256>>>(xt, W2, b2, Ws, bs, out);
}